// round 10
// baseline (speedup 1.0000x reference)
#include <cuda_runtime.h>

// Problem constants (fixed: B=128, C=1024, N=512, NUM_CLASSES=1024)
#define BB 128
#define CC 1024
#define NN 512
#define NC 1024
#define MAXL 64   // padded body-list length; actual count ~20 avg, <45 max
#define INVM 24   // max rows sharing one head atom; mean 2

#define SENT ((NN << 1) | 1)   // odd sentinel -> m = g_mt[NN][b] = 0 -> no effect on max

// ---- scratch (device globals; zero-init at load; counters self-reset) ----
__device__ float g_mt[NN + 1][BB];      // row NN stays 0 forever (sentinel row)
__device__ int   g_body_list[CC][MAXL]; // packed (n<<1)|isNeg, sentinel-padded to 64
__device__ int   g_inv_list[NN][INVM];  // packed (c<<1)|isNeg
__device__ int   g_inv_cnt[NN];         // reset by k_atoms each run

// ============ Kernel 1: prep ============
// grid = 512 CTAs x 128 threads; CTA cb handles rows c0=2cb, c1=2cb+1.
__global__ void __launch_bounds__(128) k_prep(
    const float* __restrict__ preds,
    const float* __restrict__ pos_head,
    const float* __restrict__ neg_head,
    const float* __restrict__ pos_body,
    const float* __restrict__ neg_body,
    const int*   __restrict__ atoms,     // jax downcasts int64 -> int32
    float*       __restrict__ out)
{
    const int cb = blockIdx.x;          // 0..511
    const int c0 = cb * 2, c1 = c0 + 1;
    const int t  = threadIdx.x;

    // ---- front-batched independent loads (MLP 8) ----
    const float4 p0 = ((const float4*)(pos_body + c0 * NN))[t];
    const float4 q0 = ((const float4*)(neg_body + c0 * NN))[t];
    const float4 h0 = ((const float4*)(pos_head + c0 * NN))[t];
    const float4 g0 = ((const float4*)(neg_head + c0 * NN))[t];
    const float4 p1 = ((const float4*)(pos_body + c1 * NN))[t];
    const float4 q1 = ((const float4*)(neg_body + c1 * NN))[t];
    const float4 h1 = ((const float4*)(pos_head + c1 * NN))[t];
    const float4 g1 = ((const float4*)(neg_head + c1 * NN))[t];

    // preds -> out copy: 64 float4 per CTA (threads 0..63)
    if (t < 64)
        ((float4*)out)[cb * 64 + t] = ((const float4*)preds)[cb * 64 + t];

    // g_mt gather: row n = cb (512 CTAs cover all atoms), thread t = batch b
    g_mt[cb][t] = preds[t * NC + (atoms[cb] & (NC - 1))];

    __shared__ int cnt0, cnt1;
    if (t == 0) { cnt0 = 0; cnt1 = 0; }
    __syncthreads();

    const int n0 = t * 4;

    { // compact row c0 body
        int loc[8]; int ln = 0;
        if (p0.x > 0.5f) loc[ln++] = ((n0 + 0) << 1);
        if (p0.y > 0.5f) loc[ln++] = ((n0 + 1) << 1);
        if (p0.z > 0.5f) loc[ln++] = ((n0 + 2) << 1);
        if (p0.w > 0.5f) loc[ln++] = ((n0 + 3) << 1);
        if (q0.x > 0.5f) loc[ln++] = ((n0 + 0) << 1) | 1;
        if (q0.y > 0.5f) loc[ln++] = ((n0 + 1) << 1) | 1;
        if (q0.z > 0.5f) loc[ln++] = ((n0 + 2) << 1) | 1;
        if (q0.w > 0.5f) loc[ln++] = ((n0 + 3) << 1) | 1;
        if (ln) {
            int base = atomicAdd(&cnt0, ln);
            #pragma unroll
            for (int i = 0; i < 8; i++)
                if (i < ln && base + i < MAXL) g_body_list[c0][base + i] = loc[i];
        }
    }
    { // compact row c1 body
        int loc[8]; int ln = 0;
        if (p1.x > 0.5f) loc[ln++] = ((n0 + 0) << 1);
        if (p1.y > 0.5f) loc[ln++] = ((n0 + 1) << 1);
        if (p1.z > 0.5f) loc[ln++] = ((n0 + 2) << 1);
        if (p1.w > 0.5f) loc[ln++] = ((n0 + 3) << 1);
        if (q1.x > 0.5f) loc[ln++] = ((n0 + 0) << 1) | 1;
        if (q1.y > 0.5f) loc[ln++] = ((n0 + 1) << 1) | 1;
        if (q1.z > 0.5f) loc[ln++] = ((n0 + 2) << 1) | 1;
        if (q1.w > 0.5f) loc[ln++] = ((n0 + 3) << 1) | 1;
        if (ln) {
            int base = atomicAdd(&cnt1, ln);
            #pragma unroll
            for (int i = 0; i < 8; i++)
                if (i < ln && base + i < MAXL) g_body_list[c1][base + i] = loc[i];
        }
    }

    { // head entry row c0 (exactly one nonzero across pos/neg head)
        int hm = -1;
        if (h0.x > 0.5f) hm = ((n0 + 0) << 1);
        if (h0.y > 0.5f) hm = ((n0 + 1) << 1);
        if (h0.z > 0.5f) hm = ((n0 + 2) << 1);
        if (h0.w > 0.5f) hm = ((n0 + 3) << 1);
        if (g0.x > 0.5f) hm = ((n0 + 0) << 1) | 1;
        if (g0.y > 0.5f) hm = ((n0 + 1) << 1) | 1;
        if (g0.z > 0.5f) hm = ((n0 + 2) << 1) | 1;
        if (g0.w > 0.5f) hm = ((n0 + 3) << 1) | 1;
        if (hm >= 0) {
            int n = (hm >> 1) & (NN - 1);
            int s = atomicAdd(&g_inv_cnt[n], 1);
            if (s < INVM) g_inv_list[n][s] = (c0 << 1) | (hm & 1);
        }
    }
    { // head entry row c1
        int hm = -1;
        if (h1.x > 0.5f) hm = ((n0 + 0) << 1);
        if (h1.y > 0.5f) hm = ((n0 + 1) << 1);
        if (h1.z > 0.5f) hm = ((n0 + 2) << 1);
        if (h1.w > 0.5f) hm = ((n0 + 3) << 1);
        if (g1.x > 0.5f) hm = ((n0 + 0) << 1) | 1;
        if (g1.y > 0.5f) hm = ((n0 + 1) << 1) | 1;
        if (g1.z > 0.5f) hm = ((n0 + 2) << 1) | 1;
        if (g1.w > 0.5f) hm = ((n0 + 3) << 1) | 1;
        if (hm >= 0) {
            int n = (hm >> 1) & (NN - 1);
            int s = atomicAdd(&g_inv_cnt[n], 1);
            if (s < INVM) g_inv_list[n][s] = (c1 << 1) | (hm & 1);
        }
    }

    __syncthreads();
    // sentinel-pad both lists to MAXL
    if (t < MAXL && t >= cnt0) g_body_list[c0][t] = SENT;
    if (t < MAXL && t >= cnt1) g_body_list[c1][t] = SENT;
}

// ============ Kernel 2: per-atom fused bodymin + finalize ============
// grid = NN CTAs x 128 threads (thread = b). No atomics, no fences.
// Stage all contributor body lists into smem FIRST (coalesced), then compute
// (breaks R5's serial dependent e->m chain).
__global__ void __launch_bounds__(128) k_atoms(
    const int* __restrict__ atoms,
    float*     __restrict__ out)
{
    const int n = blockIdx.x;
    const int t = threadIdx.x;

    __shared__ int   ents[INVM];
    __shared__ int   lists[INVM][MAXL];   // 24*64*4 = 6 KB
    __shared__ int   s_cn;

    if (t == 0) s_cn = min(g_inv_cnt[n], INVM);
    if (t < INVM) ents[t] = g_inv_list[n][t];
    __syncthreads();
    const int cn = s_cn;

    // Stage body lists: 2 lists per pass (64 threads each), coalesced 256B loads.
    for (int base = 0; base < cn; base += 2) {
        const int li = base + (t >> 6);          // 0 or 1 within pass
        if (li < cn) {
            const int c = (ents[li] >> 1) & (CC - 1);
            lists[li][t & 63] = g_body_list[c][t & 63];
        }
    }
    __syncthreads();

    float lbmax = 0.0f, ubmax = 0.0f;            // reference maxes include zeros
    for (int i = 0; i < cn; i++) {
        const int* L = lists[i];
        float a[8];
        #pragma unroll
        for (int j = 0; j < 8; j++) a[j] = 0.0f;

        #pragma unroll
        for (int k = 0; k < MAXL; k += 16) {
            if (L[k] == SENT) break;             // fully padded chunk -> done
            #pragma unroll
            for (int j = 0; j < 16; j++) {
                int e = L[k + j];
                float m = g_mt[e >> 1][t];       // coalesced; row NN = 0 sentinel
                float term = (e & 1) ? m : (1.0f - m);
                a[j & 7] = fmaxf(a[j & 7], term);
            }
        }
        float r0 = fmaxf(fmaxf(a[0], a[1]), fmaxf(a[2], a[3]));
        float r1 = fmaxf(fmaxf(a[4], a[5]), fmaxf(a[6], a[7]));
        const float bmin = 1.0f - fmaxf(r0, r1); // same op order as reference

        if (ents[i] & 1) ubmax = fmaxf(ubmax, bmin);
        else             lbmax = fmaxf(lbmax, bmin);
    }

    if (t == 0) g_inv_cnt[n] = 0;                // replay-safe reset

    // Unconditional finalize: cn==0 gives lb=0, ub=1 -> clamp(m)=m (exact).
    const float ub = 1.0f - ubmax;
    const float lo = fminf(lbmax, ub);
    const float hi = fmaxf(lbmax, ub);
    const float m  = g_mt[n][t];
    out[t * NC + (atoms[n] & (NC - 1))] = fmaxf(lo, fminf(hi, m));
}

extern "C" void kernel_launch(void* const* d_in, const int* in_sizes, int n_in,
                              void* d_out, int out_size)
{
    const float* preds    = (const float*)d_in[0];
    const float* pos_head = (const float*)d_in[1];
    const float* neg_head = (const float*)d_in[2];
    const float* pos_body = (const float*)d_in[3];
    const float* neg_body = (const float*)d_in[4];
    const int*   atoms    = (const int*)d_in[5];
    float* out = (float*)d_out;

    k_prep<<<NN, 128>>>(preds, pos_head, neg_head, pos_body, neg_body, atoms, out);
    k_atoms<<<NN, 128>>>(atoms, out);
}

// round 11
// speedup vs baseline: 1.1860x; 1.1860x over previous
#include <cuda_runtime.h>

// Problem constants (fixed: B=128, C=1024, N=512, NUM_CLASSES=1024)
#define BB 128
#define CC 1024
#define NN 512
#define NC 1024
#define MAXL 64   // list capacity; actual count ~20 avg, <45 max

// ---- scratch (device globals) ----
__device__ int g_list[CC][MAXL];  // packed (n<<1)|isNeg, entries [0,cnt) valid
__device__ int g_cnt[CC];
__device__ int g_head[CC];        // packed (n<<1)|isNeg (exactly one per row)

// ============ Kernel 1: build compacted lists from masks ============
// grid = 512 CTAs x 128 threads; CTA cb handles rows c0=2cb, c1=2cb+1.
__global__ void __launch_bounds__(128) k_lists(
    const float* __restrict__ pos_head,
    const float* __restrict__ neg_head,
    const float* __restrict__ pos_body,
    const float* __restrict__ neg_body)
{
    const int cb = blockIdx.x;
    const int c0 = cb * 2, c1 = c0 + 1;
    const int t  = threadIdx.x;

    // front-batched independent loads (MLP 8)
    const float4 p0 = ((const float4*)(pos_body + c0 * NN))[t];
    const float4 q0 = ((const float4*)(neg_body + c0 * NN))[t];
    const float4 h0 = ((const float4*)(pos_head + c0 * NN))[t];
    const float4 g0 = ((const float4*)(neg_head + c0 * NN))[t];
    const float4 p1 = ((const float4*)(pos_body + c1 * NN))[t];
    const float4 q1 = ((const float4*)(neg_body + c1 * NN))[t];
    const float4 h1 = ((const float4*)(pos_head + c1 * NN))[t];
    const float4 g1 = ((const float4*)(neg_head + c1 * NN))[t];

    __shared__ int cnt0, cnt1;
    if (t == 0) { cnt0 = 0; cnt1 = 0; }
    __syncthreads();

    const int n0 = t * 4;

    { // compact row c0 body
        int loc[8]; int ln = 0;
        if (p0.x > 0.5f) loc[ln++] = ((n0 + 0) << 1);
        if (p0.y > 0.5f) loc[ln++] = ((n0 + 1) << 1);
        if (p0.z > 0.5f) loc[ln++] = ((n0 + 2) << 1);
        if (p0.w > 0.5f) loc[ln++] = ((n0 + 3) << 1);
        if (q0.x > 0.5f) loc[ln++] = ((n0 + 0) << 1) | 1;
        if (q0.y > 0.5f) loc[ln++] = ((n0 + 1) << 1) | 1;
        if (q0.z > 0.5f) loc[ln++] = ((n0 + 2) << 1) | 1;
        if (q0.w > 0.5f) loc[ln++] = ((n0 + 3) << 1) | 1;
        if (ln) {
            int base = atomicAdd(&cnt0, ln);
            #pragma unroll
            for (int i = 0; i < 8; i++)
                if (i < ln && base + i < MAXL) g_list[c0][base + i] = loc[i];
        }
    }
    { // compact row c1 body
        int loc[8]; int ln = 0;
        if (p1.x > 0.5f) loc[ln++] = ((n0 + 0) << 1);
        if (p1.y > 0.5f) loc[ln++] = ((n0 + 1) << 1);
        if (p1.z > 0.5f) loc[ln++] = ((n0 + 2) << 1);
        if (p1.w > 0.5f) loc[ln++] = ((n0 + 3) << 1);
        if (q1.x > 0.5f) loc[ln++] = ((n0 + 0) << 1) | 1;
        if (q1.y > 0.5f) loc[ln++] = ((n0 + 1) << 1) | 1;
        if (q1.z > 0.5f) loc[ln++] = ((n0 + 2) << 1) | 1;
        if (q1.w > 0.5f) loc[ln++] = ((n0 + 3) << 1) | 1;
        if (ln) {
            int base = atomicAdd(&cnt1, ln);
            #pragma unroll
            for (int i = 0; i < 8; i++)
                if (i < ln && base + i < MAXL) g_list[c1][base + i] = loc[i];
        }
    }

    { // head entry row c0 (exactly one nonzero across pos/neg head)
        int hm = -1;
        if (h0.x > 0.5f) hm = ((n0 + 0) << 1);
        if (h0.y > 0.5f) hm = ((n0 + 1) << 1);
        if (h0.z > 0.5f) hm = ((n0 + 2) << 1);
        if (h0.w > 0.5f) hm = ((n0 + 3) << 1);
        if (g0.x > 0.5f) hm = ((n0 + 0) << 1) | 1;
        if (g0.y > 0.5f) hm = ((n0 + 1) << 1) | 1;
        if (g0.z > 0.5f) hm = ((n0 + 2) << 1) | 1;
        if (g0.w > 0.5f) hm = ((n0 + 3) << 1) | 1;
        if (hm >= 0) g_head[c0] = hm;     // single finder thread: race-free
    }
    { // head entry row c1
        int hm = -1;
        if (h1.x > 0.5f) hm = ((n0 + 0) << 1);
        if (h1.y > 0.5f) hm = ((n0 + 1) << 1);
        if (h1.z > 0.5f) hm = ((n0 + 2) << 1);
        if (h1.w > 0.5f) hm = ((n0 + 3) << 1);
        if (g1.x > 0.5f) hm = ((n0 + 0) << 1) | 1;
        if (g1.y > 0.5f) hm = ((n0 + 1) << 1) | 1;
        if (g1.z > 0.5f) hm = ((n0 + 2) << 1) | 1;
        if (g1.w > 0.5f) hm = ((n0 + 3) << 1) | 1;
        if (hm >= 0) g_head[c1] = hm;
    }

    __syncthreads();
    if (t == 0) {
        g_cnt[c0] = min(cnt0, MAXL);
        g_cnt[c1] = min(cnt1, MAXL);
    }
}

// ============ Kernel 2: per-batch fused (copy + bodymin + clamp) ============
// grid = BB CTAs x 256 threads. CTA = batch b. Zero cross-CTA communication:
// m gathered from CTA's own preds row; per thread exactly 4 rows (balanced);
// list loads front-batched int4 (no dependent global chain); smem atomicMax
// on spread addresses; finalize all 512 atom columns in-CTA.
__global__ void __launch_bounds__(256) k_batch(
    const float* __restrict__ preds,
    const int*   __restrict__ atoms,     // jax downcasts int64 -> int32
    float*       __restrict__ out)
{
    const int b = blockIdx.x;
    const int t = threadIdx.x;

    __shared__ float    m_s[NN];
    __shared__ unsigned lb_s[NN];
    __shared__ unsigned ub_s[NN];

    // copy preds row b -> out row b (256 float4 = whole 1024-col row)
    ((float4*)(out + b * NC))[t] = ((const float4*)(preds + b * NC))[t];

    // stage m and zero accumulators (gather WITHIN row b: L1/L2 friendly)
    #pragma unroll
    for (int r = 0; r < 2; r++) {
        const int n = t + 256 * r;
        m_s[n]  = preds[b * NC + (atoms[n] & (NC - 1))];
        lb_s[n] = 0u;
        ub_s[n] = 0u;
    }
    __syncthreads();

    // batch the per-row metadata loads (8 independent, coalesced)
    int cnts[4], heads[4];
    #pragma unroll
    for (int r = 0; r < 4; r++) {
        const int c = t + 256 * r;
        cnts[r]  = g_cnt[c];
        heads[r] = g_head[c];
    }

    // 4 rows per thread; keep row loop rolled so v[8] registers are reused
    #pragma unroll 1
    for (int r = 0; r < 4; r++) {
        const int c  = t + 256 * r;
        const int cn = min(cnts[r], MAXL);
        const int4* Lp = (const int4*)(&g_list[c][0]);   // 256B row, 16B aligned

        // front-batched list load: up to 8 independent int4 loads (32 entries)
        int4 v[8];
        #pragma unroll
        for (int w = 0; w < 8; w++)
            if (w * 4 < cn) v[w] = Lp[w];

        float a0 = 0.0f, a1 = 0.0f;      // acc init 0 = reference's dense zeros
        #pragma unroll
        for (int w = 0; w < 8; w++) {
            if (w * 4 >= cn) break;
            const int* e4 = (const int*)&v[w];
            #pragma unroll
            for (int j = 0; j < 4; j++) {
                if (w * 4 + j < cn) {
                    const int e = e4[j];
                    const float m = m_s[(e >> 1) & (NN - 1)];
                    const float term = (e & 1) ? m : (1.0f - m);
                    if (j & 1) a1 = fmaxf(a1, term);
                    else       a0 = fmaxf(a0, term);
                }
            }
        }
        // rare tail: cn > 32 (P < 1e-2 per row)
        for (int k = 32; k < cn; k++) {
            const int e = g_list[c][k];
            const float m = m_s[(e >> 1) & (NN - 1)];
            a0 = fmaxf(a0, (e & 1) ? m : (1.0f - m));
        }

        const float bmin = 1.0f - fmaxf(a0, a1);   // same op order as reference

        // scatter to head atom (exactly one per row), smem bit-pattern max
        const int hm = heads[r];
        const int n  = (hm >> 1) & (NN - 1);
        const unsigned bits = __float_as_uint(bmin);   // bmin in [0,1]
        if (hm >= 0) {
            if (hm & 1) atomicMax(&ub_s[n], bits);
            else        atomicMax(&lb_s[n], bits);
        }
    }
    __syncthreads();

    // finalize all 512 atom columns of row b (clamp; no-contributor case is
    // lb=0, ub=1 -> identity, exactly matching the reference)
    #pragma unroll
    for (int r = 0; r < 2; r++) {
        const int n = t + 256 * r;
        const float lb = __uint_as_float(lb_s[n]);
        const float ub = 1.0f - __uint_as_float(ub_s[n]);
        const float lo = fminf(lb, ub);
        const float hi = fmaxf(lb, ub);
        out[b * NC + (atoms[n] & (NC - 1))] = fmaxf(lo, fminf(hi, m_s[n]));
    }
}

extern "C" void kernel_launch(void* const* d_in, const int* in_sizes, int n_in,
                              void* d_out, int out_size)
{
    const float* preds    = (const float*)d_in[0];
    const float* pos_head = (const float*)d_in[1];
    const float* neg_head = (const float*)d_in[2];
    const float* pos_body = (const float*)d_in[3];
    const float* neg_body = (const float*)d_in[4];
    const int*   atoms    = (const int*)d_in[5];
    float* out = (float*)d_out;

    k_lists<<<NN, 128>>>(pos_head, neg_head, pos_body, neg_body);
    k_batch<<<BB, 256>>>(preds, atoms, out);
}

// round 12
// speedup vs baseline: 1.4076x; 1.1868x over previous
#include <cuda_runtime.h>

// Problem constants (fixed: B=128, C=1024, N=512, NUM_CLASSES=1024)
#define BB 128
#define CC 1024
#define NN 512
#define NC 1024
#define MAXL 64   // padded list length; actual count ~20 avg, <45 max

#define SENT ((NN << 1) | 1)   // odd sentinel -> m = g_mt[NN][b] = 0 -> no-op in max

// ---- scratch (device globals; zero-init at load; all state self-resets) ----
__device__ float    g_mt[NN + 1][BB];      // row NN stays 0 forever (sentinel row)
__device__ int      g_list[CC][MAXL];      // packed (n<<1)|isNeg, sentinel-padded
__device__ int      g_head[CC];            // packed (n<<1)|isNeg (one per row)
__device__ int      g_inv_cnt[NN];         // contributors per atom (reset by finalizer)
__device__ int      g_done[NN];            // arrivals per atom (reset by finalizer)
__device__ unsigned g_lb[NN][BB];          // fp-bit max accum (reset by finalizer)
__device__ unsigned g_ub[NN][BB];

// ============ Kernel 1: prep ============
// grid = 512 CTAs x 128 threads; CTA cb handles rows c0=2cb, c1=2cb+1.
__global__ void __launch_bounds__(128) k_prep(
    const float* __restrict__ preds,
    const float* __restrict__ pos_head,
    const float* __restrict__ neg_head,
    const float* __restrict__ pos_body,
    const float* __restrict__ neg_body,
    const int*   __restrict__ atoms,     // jax downcasts int64 -> int32
    float*       __restrict__ out)
{
    const int cb = blockIdx.x;
    const int c0 = cb * 2, c1 = c0 + 1;
    const int t  = threadIdx.x;

    // front-batched independent loads (MLP 8)
    const float4 p0 = ((const float4*)(pos_body + c0 * NN))[t];
    const float4 q0 = ((const float4*)(neg_body + c0 * NN))[t];
    const float4 h0 = ((const float4*)(pos_head + c0 * NN))[t];
    const float4 g0 = ((const float4*)(neg_head + c0 * NN))[t];
    const float4 p1 = ((const float4*)(pos_body + c1 * NN))[t];
    const float4 q1 = ((const float4*)(neg_body + c1 * NN))[t];
    const float4 h1 = ((const float4*)(pos_head + c1 * NN))[t];
    const float4 g1 = ((const float4*)(neg_head + c1 * NN))[t];

    // preds -> out copy: 64 float4 per CTA (threads 0..63)
    if (t < 64)
        ((float4*)out)[cb * 64 + t] = ((const float4*)preds)[cb * 64 + t];

    // g_mt gather: row n = cb, thread t = batch b
    g_mt[cb][t] = preds[t * NC + (atoms[cb] & (NC - 1))];

    __shared__ int cnt0, cnt1;
    if (t == 0) { cnt0 = 0; cnt1 = 0; }
    __syncthreads();

    const int n0 = t * 4;

    { // compact row c0 body
        int loc[8]; int ln = 0;
        if (p0.x > 0.5f) loc[ln++] = ((n0 + 0) << 1);
        if (p0.y > 0.5f) loc[ln++] = ((n0 + 1) << 1);
        if (p0.z > 0.5f) loc[ln++] = ((n0 + 2) << 1);
        if (p0.w > 0.5f) loc[ln++] = ((n0 + 3) << 1);
        if (q0.x > 0.5f) loc[ln++] = ((n0 + 0) << 1) | 1;
        if (q0.y > 0.5f) loc[ln++] = ((n0 + 1) << 1) | 1;
        if (q0.z > 0.5f) loc[ln++] = ((n0 + 2) << 1) | 1;
        if (q0.w > 0.5f) loc[ln++] = ((n0 + 3) << 1) | 1;
        if (ln) {
            int base = atomicAdd(&cnt0, ln);
            #pragma unroll
            for (int i = 0; i < 8; i++)
                if (i < ln && base + i < MAXL) g_list[c0][base + i] = loc[i];
        }
    }
    { // compact row c1 body
        int loc[8]; int ln = 0;
        if (p1.x > 0.5f) loc[ln++] = ((n0 + 0) << 1);
        if (p1.y > 0.5f) loc[ln++] = ((n0 + 1) << 1);
        if (p1.z > 0.5f) loc[ln++] = ((n0 + 2) << 1);
        if (p1.w > 0.5f) loc[ln++] = ((n0 + 3) << 1);
        if (q1.x > 0.5f) loc[ln++] = ((n0 + 0) << 1) | 1;
        if (q1.y > 0.5f) loc[ln++] = ((n0 + 1) << 1) | 1;
        if (q1.z > 0.5f) loc[ln++] = ((n0 + 2) << 1) | 1;
        if (q1.w > 0.5f) loc[ln++] = ((n0 + 3) << 1) | 1;
        if (ln) {
            int base = atomicAdd(&cnt1, ln);
            #pragma unroll
            for (int i = 0; i < 8; i++)
                if (i < ln && base + i < MAXL) g_list[c1][base + i] = loc[i];
        }
    }

    { // head entry row c0 (exactly one nonzero across pos/neg head)
        int hm = -1;
        if (h0.x > 0.5f) hm = ((n0 + 0) << 1);
        if (h0.y > 0.5f) hm = ((n0 + 1) << 1);
        if (h0.z > 0.5f) hm = ((n0 + 2) << 1);
        if (h0.w > 0.5f) hm = ((n0 + 3) << 1);
        if (g0.x > 0.5f) hm = ((n0 + 0) << 1) | 1;
        if (g0.y > 0.5f) hm = ((n0 + 1) << 1) | 1;
        if (g0.z > 0.5f) hm = ((n0 + 2) << 1) | 1;
        if (g0.w > 0.5f) hm = ((n0 + 3) << 1) | 1;
        if (hm >= 0) {                    // one finder thread per row
            g_head[c0] = hm;
            atomicAdd(&g_inv_cnt[(hm >> 1) & (NN - 1)], 1);
        }
    }
    { // head entry row c1
        int hm = -1;
        if (h1.x > 0.5f) hm = ((n0 + 0) << 1);
        if (h1.y > 0.5f) hm = ((n0 + 1) << 1);
        if (h1.z > 0.5f) hm = ((n0 + 2) << 1);
        if (h1.w > 0.5f) hm = ((n0 + 3) << 1);
        if (g1.x > 0.5f) hm = ((n0 + 0) << 1) | 1;
        if (g1.y > 0.5f) hm = ((n0 + 1) << 1) | 1;
        if (g1.z > 0.5f) hm = ((n0 + 2) << 1) | 1;
        if (g1.w > 0.5f) hm = ((n0 + 3) << 1) | 1;
        if (hm >= 0) {
            g_head[c1] = hm;
            atomicAdd(&g_inv_cnt[(hm >> 1) & (NN - 1)], 1);
        }
    }

    __syncthreads();
    // sentinel-pad both lists to MAXL
    if (t < MAXL && t >= cnt0) g_list[c0][t] = SENT;
    if (t < MAXL && t >= cnt1) g_list[c1][t] = SENT;
}

// Body min over one 64-entry sentinel-padded smem list; thread = b.
// Coalesced g_mt row loads, 8 independent accumulators (fmax exact on [0,1]).
__device__ __forceinline__ float body_min_of(const int* L, int t)
{
    float a[8];
    #pragma unroll
    for (int j = 0; j < 8; j++) a[j] = 0.0f;

    #pragma unroll
    for (int k = 0; k < MAXL; k += 16) {
        if (L[k] == SENT) break;          // fully padded chunk -> done
        #pragma unroll
        for (int j = 0; j < 16; j++) {
            int e = L[k + j];
            float m = g_mt[e >> 1][t];    // e>>1 <= NN; row NN = 0
            float term = (e & 1) ? m : (1.0f - m);
            a[j & 7] = fmaxf(a[j & 7], term);
        }
    }
    float r0 = fmaxf(fmaxf(a[0], a[1]), fmaxf(a[2], a[3]));
    float r1 = fmaxf(fmaxf(a[4], a[5]), fmaxf(a[6], a[7]));
    return 1.0f - fmaxf(r0, r1);          // same op order as reference (1 - max)
}

// ============ Kernel 2: bodymin + RED scatter + last-arriver finalize ============
// grid = 512 CTAs x 128 threads (thread = b). CTA cb handles rows 2cb, 2cb+1.
__global__ void __launch_bounds__(128) k_body(
    const int* __restrict__ atoms,
    float*     __restrict__ out)
{
    const int cb = blockIdx.x;
    const int c0 = cb * 2;
    const int t  = threadIdx.x;

    __shared__ int lst[2 * MAXL];
    __shared__ int s_last0, s_last1;

    // ONE coalesced 512B load covers both rows' lists
    lst[t] = g_list[c0][0 * MAXL + t];   // g_list rows contiguous: [c0][64]+[c1][64]
    const int hm0 = g_head[c0];
    const int hm1 = g_head[c0 + 1];
    __syncthreads();

    const float bmin0 = body_min_of(lst, t);
    const float bmin1 = body_min_of(lst + MAXL, t);

    const int na = (hm0 >> 1) & (NN - 1);
    const int nb = (hm1 >> 1) & (NN - 1);

    // fire-and-forget reductions (no return value used -> REDG)
    if (hm0 >= 0) {
        if (hm0 & 1) atomicMax(&g_ub[na][t], __float_as_uint(bmin0));
        else         atomicMax(&g_lb[na][t], __float_as_uint(bmin0));
    }
    if (hm1 >= 0) {
        if (hm1 & 1) atomicMax(&g_ub[nb][t], __float_as_uint(bmin1));
        else         atomicMax(&g_lb[nb][t], __float_as_uint(bmin1));
    }

    // release maxes, then arrive (2 counters per CTA, parallel warps)
    __threadfence();
    __syncthreads();
    if (t == 0)
        s_last0 = (hm0 >= 0) && (atomicAdd(&g_done[na], 1) == g_inv_cnt[na] - 1);
    if (t == 64)
        s_last1 = (hm1 >= 0) && (atomicAdd(&g_done[nb], 1) == g_inv_cnt[nb] - 1);
    __syncthreads();

    // last arriver per atom finalizes that atom's output column + resets state
    if (s_last0) {
        __threadfence();   // acquire
        const float lb = __uint_as_float(*(volatile unsigned*)&g_lb[na][t]);
        const float ub = 1.0f - __uint_as_float(*(volatile unsigned*)&g_ub[na][t]);
        const float lo = fminf(lb, ub);
        const float hi = fmaxf(lb, ub);
        out[t * NC + (atoms[na] & (NC - 1))] = fmaxf(lo, fminf(hi, g_mt[na][t]));
        g_lb[na][t] = 0u; g_ub[na][t] = 0u;                  // replay-safe reset
        if (t == 0) { g_done[na] = 0; g_inv_cnt[na] = 0; }
    }
    if (s_last1) {
        __threadfence();
        const float lb = __uint_as_float(*(volatile unsigned*)&g_lb[nb][t]);
        const float ub = 1.0f - __uint_as_float(*(volatile unsigned*)&g_ub[nb][t]);
        const float lo = fminf(lb, ub);
        const float hi = fmaxf(lb, ub);
        out[t * NC + (atoms[nb] & (NC - 1))] = fmaxf(lo, fminf(hi, g_mt[nb][t]));
        g_lb[nb][t] = 0u; g_ub[nb][t] = 0u;
        if (t == 0) { g_done[nb] = 0; g_inv_cnt[nb] = 0; }
    }
    // atoms with no contributors: clamp is identity -> copied preds is correct
}

extern "C" void kernel_launch(void* const* d_in, const int* in_sizes, int n_in,
                              void* d_out, int out_size)
{
    const float* preds    = (const float*)d_in[0];
    const float* pos_head = (const float*)d_in[1];
    const float* neg_head = (const float*)d_in[2];
    const float* pos_body = (const float*)d_in[3];
    const float* neg_body = (const float*)d_in[4];
    const int*   atoms    = (const int*)d_in[5];
    float* out = (float*)d_out;

    k_prep<<<NN, 128>>>(preds, pos_head, neg_head, pos_body, neg_body, atoms, out);
    k_body<<<NN, 128>>>(atoms, out);
}

// round 13
// speedup vs baseline: 1.6617x; 1.1805x over previous
#include <cuda_runtime.h>

// Problem constants (fixed: B=128, C=1024, N=512, NUM_CLASSES=1024)
#define BB 128
#define CC 1024
#define NN 512
#define NC 1024
#define MAXL 64   // smem list capacity; actual count ~20 avg, <45 max

#define SENT ((NN << 1) | 1)   // odd sentinel -> m = g_mt[NN][b] = 0 -> no-op in max

// ---- scratch (device globals; zero-init at load; all state self-resets) ----
__device__ float    g_mt[NN + 1][BB];   // row NN stays 0 forever (sentinel row)
__device__ int      g_head[CC];         // packed (n<<1)|isNeg (one per row)
__device__ int      g_inv_cnt[NN];      // contributors per atom (reset by finalizer)
__device__ int      g_done[NN];         // arrivals per atom (reset by finalizer)
__device__ unsigned g_lb[NN][BB];       // fp-bit max accum (reset by finalizer)
__device__ unsigned g_ub[NN][BB];

// ============ Node 1: heads + transpose + copy ============
// grid = 512 CTAs x 128 threads; CTA cb handles head rows c0=2cb, c1=2cb+1.
__global__ void __launch_bounds__(128) k_head(
    const float* __restrict__ preds,
    const float* __restrict__ pos_head,
    const float* __restrict__ neg_head,
    const int*   __restrict__ atoms,     // jax downcasts int64 -> int32
    float*       __restrict__ out)
{
    const int cb = blockIdx.x;
    const int c0 = cb * 2, c1 = c0 + 1;
    const int t  = threadIdx.x;

    // front-batched independent loads (head masks only: 4MB total)
    const float4 h0 = ((const float4*)(pos_head + c0 * NN))[t];
    const float4 g0 = ((const float4*)(neg_head + c0 * NN))[t];
    const float4 h1 = ((const float4*)(pos_head + c1 * NN))[t];
    const float4 g1 = ((const float4*)(neg_head + c1 * NN))[t];

    // preds -> out copy: 64 float4 per CTA (threads 0..63 cover all 32768)
    if (t < 64)
        ((float4*)out)[cb * 64 + t] = ((const float4*)preds)[cb * 64 + t];

    // g_mt transpose gather: row n = cb, thread t = batch b (coalesced column)
    g_mt[cb][t] = preds[t * NC + (atoms[cb] & (NC - 1))];

    const int n0 = t * 4;
    { // head entry row c0 (exactly one nonzero across pos/neg head)
        int hm = -1;
        if (h0.x > 0.5f) hm = ((n0 + 0) << 1);
        if (h0.y > 0.5f) hm = ((n0 + 1) << 1);
        if (h0.z > 0.5f) hm = ((n0 + 2) << 1);
        if (h0.w > 0.5f) hm = ((n0 + 3) << 1);
        if (g0.x > 0.5f) hm = ((n0 + 0) << 1) | 1;
        if (g0.y > 0.5f) hm = ((n0 + 1) << 1) | 1;
        if (g0.z > 0.5f) hm = ((n0 + 2) << 1) | 1;
        if (g0.w > 0.5f) hm = ((n0 + 3) << 1) | 1;
        if (hm >= 0) {                        // single finder thread: race-free
            g_head[c0] = hm;
            atomicAdd(&g_inv_cnt[(hm >> 1) & (NN - 1)], 1);
        }
    }
    { // head entry row c1
        int hm = -1;
        if (h1.x > 0.5f) hm = ((n0 + 0) << 1);
        if (h1.y > 0.5f) hm = ((n0 + 1) << 1);
        if (h1.z > 0.5f) hm = ((n0 + 2) << 1);
        if (h1.w > 0.5f) hm = ((n0 + 3) << 1);
        if (g1.x > 0.5f) hm = ((n0 + 0) << 1) | 1;
        if (g1.y > 0.5f) hm = ((n0 + 1) << 1) | 1;
        if (g1.z > 0.5f) hm = ((n0 + 2) << 1) | 1;
        if (g1.w > 0.5f) hm = ((n0 + 3) << 1) | 1;
        if (hm >= 0) {
            g_head[c1] = hm;
            atomicAdd(&g_inv_cnt[(hm >> 1) & (NN - 1)], 1);
        }
    }
}

// ============ Node 2: body masks -> bmin -> scatter -> finalize ============
// grid = 1024 CTAs x 128 threads (thread = b). One row per CTA: max grid
// parallelism, shortest serial chain. Lists never leave SMEM.
__global__ void __launch_bounds__(128) k_body(
    const float* __restrict__ pos_body,
    const float* __restrict__ neg_body,
    const int*   __restrict__ atoms,
    float*       __restrict__ out)
{
    const int c = blockIdx.x;
    const int t = threadIdx.x;

    // front-batched loads: body masks for row c + head entry
    const float4 p = ((const float4*)(pos_body + c * NN))[t];
    const float4 q = ((const float4*)(neg_body + c * NN))[t];
    const int   hm = g_head[c];

    __shared__ int cnt;
    __shared__ int lst[MAXL];
    __shared__ int s_last;
    if (t == 0) cnt = 0;
    __syncthreads();

    // compact this thread's 4 columns into smem list (order-free: exact max)
    const int n0 = t * 4;
    int loc[8]; int ln = 0;
    if (p.x > 0.5f) loc[ln++] = ((n0 + 0) << 1);
    if (p.y > 0.5f) loc[ln++] = ((n0 + 1) << 1);
    if (p.z > 0.5f) loc[ln++] = ((n0 + 2) << 1);
    if (p.w > 0.5f) loc[ln++] = ((n0 + 3) << 1);
    if (q.x > 0.5f) loc[ln++] = ((n0 + 0) << 1) | 1;
    if (q.y > 0.5f) loc[ln++] = ((n0 + 1) << 1) | 1;
    if (q.z > 0.5f) loc[ln++] = ((n0 + 2) << 1) | 1;
    if (q.w > 0.5f) loc[ln++] = ((n0 + 3) << 1) | 1;
    if (ln) {
        int base = atomicAdd(&cnt, ln);
        #pragma unroll
        for (int i = 0; i < 8; i++)
            if (i < ln && base + i < MAXL) lst[base + i] = loc[i];
    }
    __syncthreads();
    if (t < MAXL && t >= cnt) lst[t] = SENT;   // sentinel-pad
    __syncthreads();

    // bmin for batch b=t: chunked loop, 8 independent accumulators,
    // coalesced g_mt row loads (exact: fmax associative on [0,1])
    float a[8];
    #pragma unroll
    for (int j = 0; j < 8; j++) a[j] = 0.0f;
    #pragma unroll
    for (int k = 0; k < MAXL; k += 16) {
        if (lst[k] == SENT) break;
        #pragma unroll
        for (int j = 0; j < 16; j++) {
            int e = lst[k + j];
            float m = g_mt[e >> 1][t];          // e>>1 <= NN; row NN = 0
            float term = (e & 1) ? m : (1.0f - m);
            a[j & 7] = fmaxf(a[j & 7], term);
        }
    }
    float r0 = fmaxf(fmaxf(a[0], a[1]), fmaxf(a[2], a[3]));
    float r1 = fmaxf(fmaxf(a[4], a[5]), fmaxf(a[6], a[7]));
    const float bmin = 1.0f - fmaxf(r0, r1);    // same op order as reference

    // fire-and-forget max reduction to head atom n (bit-pattern max, [0,1])
    const int n = (hm >> 1) & (NN - 1);
    if (hm >= 0) {
        if (hm & 1) atomicMax(&g_ub[n][t], __float_as_uint(bmin));
        else        atomicMax(&g_lb[n][t], __float_as_uint(bmin));
    }

    // release maxes, then arrive on n's done counter
    __threadfence();
    __syncthreads();
    if (t == 0)
        s_last = (hm >= 0) && (atomicAdd(&g_done[n], 1) == g_inv_cnt[n] - 1);
    __syncthreads();

    // last arriver for atom n finalizes the output column + resets state
    if (s_last) {
        __threadfence();   // acquire
        const float lb = __uint_as_float(*(volatile unsigned*)&g_lb[n][t]);
        const float ub = 1.0f - __uint_as_float(*(volatile unsigned*)&g_ub[n][t]);
        const float lo = fminf(lb, ub);
        const float hi = fmaxf(lb, ub);
        out[t * NC + (atoms[n] & (NC - 1))] = fmaxf(lo, fminf(hi, g_mt[n][t]));
        g_lb[n][t] = 0u; g_ub[n][t] = 0u;                   // replay-safe reset
        if (t == 0) { g_done[n] = 0; g_inv_cnt[n] = 0; }
    }
    // atoms with no contributors: clamp is identity -> copied preds is correct
}

extern "C" void kernel_launch(void* const* d_in, const int* in_sizes, int n_in,
                              void* d_out, int out_size)
{
    const float* preds    = (const float*)d_in[0];
    const float* pos_head = (const float*)d_in[1];
    const float* neg_head = (const float*)d_in[2];
    const float* pos_body = (const float*)d_in[3];
    const float* neg_body = (const float*)d_in[4];
    const int*   atoms    = (const int*)d_in[5];
    float* out = (float*)d_out;

    k_head<<<NN, 128>>>(preds, pos_head, neg_head, atoms, out);
    k_body<<<CC, 128>>>(pos_body, neg_body, atoms, out);
}